// round 10
// baseline (speedup 1.0000x reference)
#include <cuda_runtime.h>
#include <math.h>
#include <float.h>
#include <stdint.h>

#define B_    4
#define NIN_  4096
#define M_    16384
#define CIN_  256
#define COUT_ 128
#define NSEG_ 4
#define SEGC_ (NIN_ / NSEG_)   // 1024 candidates per segment

typedef unsigned long long ull;

// ---------------- f32x2 packed helpers ----------------
__device__ __forceinline__ ull pack2(float lo, float hi) {
    ull r; asm("mov.b64 %0,{%1,%2};" : "=l"(r) : "f"(lo), "f"(hi)); return r;
}
__device__ __forceinline__ void unpack2(float& lo, float& hi, ull v) {
    asm("mov.b64 {%0,%1},%2;" : "=f"(lo), "=f"(hi) : "l"(v));
}
__device__ __forceinline__ ull fma2(ull a, ull b, ull c) {
    ull d; asm("fma.rn.f32x2 %0,%1,%2,%3;" : "=l"(d) : "l"(a), "l"(b), "l"(c)); return d;
}
__device__ __forceinline__ ull mul2(ull a, ull b) {
    ull d; asm("mul.rn.f32x2 %0,%1,%2;" : "=l"(d) : "l"(a), "l"(b)); return d;
}
__device__ __forceinline__ ull add2(ull a, ull b) {
    ull d; asm("add.rn.f32x2 %0,%1,%2;" : "=l"(d) : "l"(a), "l"(b)); return d;
}

// ---------------- scratch ----------------
__device__ float g_bufA[B_ * COUT_ * NIN_];
__device__ float g_bufB[B_ * COUT_ * NIN_];
__device__ float g_featT[B_ * NIN_ * COUT_];
__device__ float g_pval[B_ * NSEG_ * M_ * 3];
__device__ int   g_pidx[B_ * NSEG_ * M_ * 3];

// ---------------- fused Conv1d(k=1) + BN + ReLU GEMM ----------------
// Tile 128 cout x 32 n, 256 threads, 8x2 micro-tile. Same per-output FMA
// chain over k as before -> bitwise identical results; 2x blocks for
// occupancy and ~50 regs so it co-resides with scan blocks.
__global__ __launch_bounds__(256) void mlp_kernel(
    const float* __restrict__ X, const float* __restrict__ W,
    const float* __restrict__ bias, const float* __restrict__ gamma,
    const float* __restrict__ betap, const float* __restrict__ rmean,
    const float* __restrict__ rvar, float* __restrict__ Y,
    int K, int transposed)
{
    __shared__ float Ws[32][COUT_];
    __shared__ float Xs[32][32];
    const int tid = threadIdx.x;
    const int b   = blockIdx.y;
    const int n0  = blockIdx.x * 32;
    const float* Xb = X + (size_t)b * K * NIN_;

    ull acc2[4][2];
#pragma unroll
    for (int p = 0; p < 4; p++)
#pragma unroll
        for (int j = 0; j < 2; j++) acc2[p][j] = 0ull;

    const int rg    = tid >> 4;    // 0..15
    const int cg    = tid & 15;    // 0..15
    const int cout0 = rg * 8;
    const int nl    = cg * 2;

    const int xnq = tid & 7;       // 0..7  (n quad)
    const int xkk = tid >> 3;      // 0..31 (k row)

    for (int k0 = 0; k0 < K; k0 += 32) {
#pragma unroll
        for (int l = 0; l < 4; l++) {
            int idx = tid + l * 256;
            int co  = idx & 127;
            int kq  = idx >> 7;
            float4 w4 = *(const float4*)(W + (size_t)co * K + k0 + kq * 4);
            Ws[kq * 4 + 0][co] = w4.x;
            Ws[kq * 4 + 1][co] = w4.y;
            Ws[kq * 4 + 2][co] = w4.z;
            Ws[kq * 4 + 3][co] = w4.w;
        }
        *(float4*)&Xs[xkk][xnq * 4] =
            *(const float4*)(Xb + (size_t)(k0 + xkk) * NIN_ + n0 + xnq * 4);
        __syncthreads();
#pragma unroll
        for (int k = 0; k < 32; k++) {
            ull ap[4];
#pragma unroll
            for (int p = 0; p < 4; p++)
                ap[p] = *(const ull*)&Ws[k][cout0 + 2 * p];
            float2 xb = *(const float2*)&Xs[k][nl];
            ull xd[2];
            xd[0] = pack2(xb.x, xb.x);
            xd[1] = pack2(xb.y, xb.y);
#pragma unroll
            for (int p = 0; p < 4; p++)
#pragma unroll
                for (int j = 0; j < 2; j++)
                    acc2[p][j] = fma2(ap[p], xd[j], acc2[p][j]);
        }
        __syncthreads();
    }

    float acc[8][2];
#pragma unroll
    for (int p = 0; p < 4; p++)
#pragma unroll
        for (int j = 0; j < 2; j++)
            unpack2(acc[2 * p][j], acc[2 * p + 1][j], acc2[p][j]);

    float sc[8], shf[8];
#pragma unroll
    for (int i = 0; i < 8; i++) {
        int c = cout0 + i;
        float s = gamma[c] / sqrtf(rvar[c] + 1e-5f);
        sc[i]  = s;
        shf[i] = betap[c] + (bias[c] - rmean[c]) * s;
    }

    if (!transposed) {
#pragma unroll
        for (int i = 0; i < 8; i++) {
            float2 v;
            v.x = fmaxf(__fmaf_rn(acc[i][0], sc[i], shf[i]), 0.f);
            v.y = fmaxf(__fmaf_rn(acc[i][1], sc[i], shf[i]), 0.f);
            *(float2*)(Y + ((size_t)b * COUT_ + cout0 + i) * NIN_ + n0 + nl) = v;
        }
    } else {
#pragma unroll
        for (int j = 0; j < 2; j++) {
            float v[8];
#pragma unroll
            for (int i = 0; i < 8; i++)
                v[i] = fmaxf(__fmaf_rn(acc[i][j], sc[i], shf[i]), 0.f);
            float* p = Y + ((size_t)b * NIN_ + n0 + nl + j) * COUT_ + cout0;
            *(float4*)(p)     = make_float4(v[0], v[1], v[2], v[3]);
            *(float4*)(p + 4) = make_float4(v[4], v[5], v[6], v[7]);
        }
    }
}

// ---------------- segmented exact top-3 scan (group-4 deferred compare) ----------------
// Per 4 candidates per query: compute both packed d2 pairs (values stay in
// registers), one min-of-4 + one compare + one branch; on the rare trigger,
// clamp and strict-<-insert the 4 held values in ascending index order ->
// selection bitwise identical to the sequential reference scan.
#define INSERT3(d_, j_, s0_, s1_, s2_, i0_, i1_, i2_)                      \
    if (d_ < s2_) {                                                        \
        if (d_ < s1_) {                                                    \
            s2_ = s1_; i2_ = i1_;                                          \
            if (d_ < s0_) { s1_ = s0_; i1_ = i0_; s0_ = d_; i0_ = j_; }    \
            else          { s1_ = d_;  i1_ = j_; }                         \
        } else { s2_ = d_; i2_ = j_; }                                     \
    }

#define GROUP4(D0, D1, D2, D3, JB, S0, S1, S2, I0, I1, I2)                 \
    {                                                                      \
        float m_ = fminf(fminf(D0, D1), fminf(D2, D3));                    \
        if (__builtin_expect(m_ < S2, 0)) {                                \
            float c0 = (D0 < 0.0f) ? 1e-7f : D0;                           \
            float c1 = (D1 < 0.0f) ? 1e-7f : D1;                           \
            float c2 = (D2 < 0.0f) ? 1e-7f : D2;                           \
            float c3 = (D3 < 0.0f) ? 1e-7f : D3;                           \
            INSERT3(c0, (JB) + 0, S0, S1, S2, I0, I1, I2);                 \
            INSERT3(c1, (JB) + 1, S0, S1, S2, I0, I1, I2);                 \
            INSERT3(c2, (JB) + 2, S0, S1, S2, I0, I1, I2);                 \
            INSERT3(c3, (JB) + 3, S0, S1, S2, I0, I1, I2);                 \
        }                                                                  \
    }

__global__ __launch_bounds__(256) void scan_kernel(
    const float* __restrict__ xyzin, const float* __restrict__ xyzout,
    float* __restrict__ pval, int* __restrict__ pidx)
{
    __shared__ __align__(16) float xs[SEGC_];
    __shared__ __align__(16) float ys[SEGC_];
    __shared__ __align__(16) float zs[SEGC_];
    __shared__ __align__(16) float ss[SEGC_];

    const int tid = threadIdx.x;
    const int seg = blockIdx.y;
    const int b   = blockIdx.z;
    const int jbase = seg * SEGC_;
    const float* pin = xyzin + ((size_t)b * NIN_ + jbase) * 3;

    for (int j = tid; j < SEGC_; j += 256) {
        float x = pin[j * 3 + 0];
        float y = pin[j * 3 + 1];
        float z = pin[j * 3 + 2];
        xs[j] = x; ys[j] = y; zs[j] = z;
        ss[j] = __fadd_rn(__fadd_rn(__fmul_rn(x, x), __fmul_rn(y, y)),
                          __fmul_rn(z, z));
    }
    __syncthreads();

    const int m0 = blockIdx.x * 512 + tid;
    const int m1 = m0 + 256;

    const float* q0 = xyzout + ((size_t)b * M_ + m0) * 3;
    const float* q1 = xyzout + ((size_t)b * M_ + m1) * 3;
    float q0x = q0[0], q0y = q0[1], q0z = q0[2];
    float q1x = q1[0], q1y = q1[1], q1z = q1[2];
    float q0n = __fadd_rn(__fadd_rn(__fmul_rn(q0x, q0x), __fmul_rn(q0y, q0y)),
                          __fmul_rn(q0z, q0z));
    float q1n = __fadd_rn(__fadd_rn(__fmul_rn(q1x, q1x), __fmul_rn(q1y, q1y)),
                          __fmul_rn(q1z, q1z));

    const ull qx20 = pack2(q0x, q0x), qy20 = pack2(q0y, q0y);
    const ull qz20 = pack2(q0z, q0z), qn20 = pack2(q0n, q0n);
    const ull qx21 = pack2(q1x, q1x), qy21 = pack2(q1y, q1y);
    const ull qz21 = pack2(q1z, q1z), qn21 = pack2(q1n, q1n);
    const ull n22  = pack2(-2.0f, -2.0f);

    float a_s0 = FLT_MAX, a_s1 = FLT_MAX, a_s2 = FLT_MAX;
    float b_s0 = FLT_MAX, b_s1 = FLT_MAX, b_s2 = FLT_MAX;
    int a_i0 = 0, a_i1 = 0, a_i2 = 0;
    int b_i0 = 0, b_i1 = 0, b_i2 = 0;

    const ulonglong2* xs4 = (const ulonglong2*)xs;
    const ulonglong2* ys4 = (const ulonglong2*)ys;
    const ulonglong2* zs4 = (const ulonglong2*)zs;
    const ulonglong2* ss4 = (const ulonglong2*)ss;

#pragma unroll 2
    for (int jq = 0; jq < SEGC_ / 4; jq++) {
        ulonglong2 xq = xs4[jq], yq = ys4[jq], zq = zs4[jq], sq = ss4[jq];
        int j = jbase + 4 * jq;
        // query 0: compute all 4 distances, then one deferred check
        {
            ull dot0 = fma2(qz20, zq.x, fma2(qy20, yq.x, mul2(qx20, xq.x)));
            ull dv0  = fma2(n22, dot0, add2(qn20, sq.x));
            ull dot1 = fma2(qz20, zq.y, fma2(qy20, yq.y, mul2(qx20, xq.y)));
            ull dv1  = fma2(n22, dot1, add2(qn20, sq.y));
            float d0, d1, d2, d3;
            unpack2(d0, d1, dv0);
            unpack2(d2, d3, dv1);
            GROUP4(d0, d1, d2, d3, j, a_s0, a_s1, a_s2, a_i0, a_i1, a_i2);
        }
        // query 1
        {
            ull dot0 = fma2(qz21, zq.x, fma2(qy21, yq.x, mul2(qx21, xq.x)));
            ull dv0  = fma2(n22, dot0, add2(qn21, sq.x));
            ull dot1 = fma2(qz21, zq.y, fma2(qy21, yq.y, mul2(qx21, xq.y)));
            ull dv1  = fma2(n22, dot1, add2(qn21, sq.y));
            float d0, d1, d2, d3;
            unpack2(d0, d1, dv0);
            unpack2(d2, d3, dv1);
            GROUP4(d0, d1, d2, d3, j, b_s0, b_s1, b_s2, b_i0, b_i1, b_i2);
        }
    }

    {
        size_t o = (((size_t)b * NSEG_ + seg) * M_ + m0) * 3;
        pval[o + 0] = a_s0; pval[o + 1] = a_s1; pval[o + 2] = a_s2;
        pidx[o + 0] = a_i0; pidx[o + 1] = a_i1; pidx[o + 2] = a_i2;
    }
    {
        size_t o = (((size_t)b * NSEG_ + seg) * M_ + m1) * 3;
        pval[o + 0] = b_s0; pval[o + 1] = b_s1; pval[o + 2] = b_s2;
        pidx[o + 0] = b_i0; pidx[o + 1] = b_i1; pidx[o + 2] = b_i2;
    }
}

// ---------------- fused merge + gather + weighted interpolation ----------------
__global__ __launch_bounds__(128) void interp_kernel(
    const float* __restrict__ featT,
    const float* __restrict__ pval, const int* __restrict__ pidx,
    float* __restrict__ out)
{
    __shared__ float sacc[64][COUT_ + 1];
    __shared__ float sw[64 * 3];
    __shared__ int   si[64 * 3];
    const int tid = threadIdx.x;
    const int b   = blockIdx.y;
    const int m0  = blockIdx.x * 64;

    if (tid < 64) {
        const int m = m0 + tid;
        float v[NSEG_ * 3];
        int   ix[NSEG_ * 3];
#pragma unroll
        for (int s = 0; s < NSEG_; s++) {
            size_t o = (((size_t)b * NSEG_ + s) * M_ + m) * 3;
#pragma unroll
            for (int k = 0; k < 3; k++) {
                v[s * 3 + k]  = pval[o + k];
                ix[s * 3 + k] = pidx[o + k];
            }
        }
        float rs[3]; int ri[3];
#pragma unroll
        for (int k = 0; k < 3; k++) {
            int best = 0;
#pragma unroll
            for (int t = 1; t < NSEG_ * 3; t++) {
                bool better = (v[t] < v[best]) ||
                              (v[t] == v[best] && ix[t] < ix[best]);
                if (better) best = t;
            }
            rs[k] = v[best]; ri[k] = ix[best];
            v[best] = FLT_MAX; ix[best] = 0x7FFFFFFF;
        }
        float w0 = __fdiv_rn(1.0f, rs[0]);
        float w1 = __fdiv_rn(1.0f, rs[1]);
        float w2 = __fdiv_rn(1.0f, rs[2]);
        float wsum = __fadd_rn(__fadd_rn(w0, w1), w2);
        sw[tid * 3 + 0] = __fdiv_rn(w0, wsum);
        sw[tid * 3 + 1] = __fdiv_rn(w1, wsum);
        sw[tid * 3 + 2] = __fdiv_rn(w2, wsum);
        si[tid * 3 + 0] = ri[0];
        si[tid * 3 + 1] = ri[1];
        si[tid * 3 + 2] = ri[2];
    }
    __syncthreads();

    const float* fb = featT + (size_t)b * NIN_ * COUT_;
    const int c = tid;
#pragma unroll 2
    for (int qq = 0; qq < 64; qq++) {
        float w0 = sw[qq * 3], w1 = sw[qq * 3 + 1], w2 = sw[qq * 3 + 2];
        const float* f0 = fb + (size_t)si[qq * 3]     * COUT_;
        const float* f1 = fb + (size_t)si[qq * 3 + 1] * COUT_;
        const float* f2 = fb + (size_t)si[qq * 3 + 2] * COUT_;
        sacc[qq][c] = __fmaf_rn(w2, f2[c],
                      __fmaf_rn(w1, f1[c], __fmul_rn(w0, f0[c])));
    }
    __syncthreads();

#pragma unroll
    for (int cc = 0; cc < COUT_; cc += 2) {
        int ci = cc + (tid >> 6);
        int mi = tid & 63;
        out[((size_t)b * COUT_ + ci) * M_ + m0 + mi] = sacc[mi][ci];
    }
}

// ---------------- launch (stream-forked: scan || mlp chain) ----------------
extern "C" void kernel_launch(void* const* d_in, const int* in_sizes, int n_in,
                              void* d_out, int out_size)
{
    (void)in_sizes; (void)n_in; (void)out_size;
    const float* rgb    = (const float*)d_in[0];
    const float* xyzin  = (const float*)d_in[1];
    const float* xyzout = (const float*)d_in[2];
    const float* w1 = (const float*)d_in[3];
    const float* b1 = (const float*)d_in[4];
    const float* g1 = (const float*)d_in[5];
    const float* be1 = (const float*)d_in[6];
    const float* rm1 = (const float*)d_in[7];
    const float* rv1 = (const float*)d_in[8];
    const float* w2 = (const float*)d_in[9];
    const float* b2 = (const float*)d_in[10];
    const float* g2 = (const float*)d_in[11];
    const float* be2 = (const float*)d_in[12];
    const float* rm2 = (const float*)d_in[13];
    const float* rv2 = (const float*)d_in[14];
    const float* w3 = (const float*)d_in[15];
    const float* b3 = (const float*)d_in[16];
    const float* g3 = (const float*)d_in[17];
    const float* be3 = (const float*)d_in[18];
    const float* rm3 = (const float*)d_in[19];
    const float* rv3 = (const float*)d_in[20];
    float* out = (float*)d_out;

    float *bufA, *bufB, *featT, *pvp;
    int *pip;
    cudaGetSymbolAddress((void**)&bufA,  g_bufA);
    cudaGetSymbolAddress((void**)&bufB,  g_bufB);
    cudaGetSymbolAddress((void**)&featT, g_featT);
    cudaGetSymbolAddress((void**)&pvp,   g_pval);
    cudaGetSymbolAddress((void**)&pip,   g_pidx);

    static cudaStream_t s_side = nullptr;
    static cudaEvent_t  ev_fork = nullptr, ev_join = nullptr;
    if (s_side == nullptr) {
        cudaStreamCreateWithFlags(&s_side, cudaStreamNonBlocking);
        cudaEventCreateWithFlags(&ev_fork, cudaEventDisableTiming);
        cudaEventCreateWithFlags(&ev_join, cudaEventDisableTiming);
    }

    cudaEventRecord(ev_fork, 0);
    cudaStreamWaitEvent(s_side, ev_fork, 0);

    // side stream: 3-NN scan
    dim3 scan_grid(M_ / 512, NSEG_, B_);
    scan_kernel<<<scan_grid, 256, 0, s_side>>>(xyzin, xyzout, pvp, pip);
    cudaEventRecord(ev_join, s_side);

    // default stream: MLP chain (concurrent with scan)
    dim3 gemm_grid(NIN_ / 32, B_);
    mlp_kernel<<<gemm_grid, 256>>>(rgb,  w1, b1, g1, be1, rm1, rv1, bufA,  CIN_,  0);
    mlp_kernel<<<gemm_grid, 256>>>(bufA, w2, b2, g2, be2, rm2, rv2, bufB,  COUT_, 0);
    mlp_kernel<<<gemm_grid, 256>>>(bufB, w3, b3, g3, be3, rm3, rv3, featT, COUT_, 1);

    cudaStreamWaitEvent(0, ev_join, 0);

    dim3 interp_grid(M_ / 64, B_);
    interp_kernel<<<interp_grid, 128>>>(featT, pvp, pip, out);
}

// round 11
// speedup vs baseline: 1.0365x; 1.0365x over previous
#include <cuda_runtime.h>
#include <cuda_bf16.h>
#include <math.h>
#include <float.h>
#include <stdint.h>

#define B_    4
#define NIN_  4096
#define M_    16384
#define CIN_  256
#define COUT_ 128
#define NSEG_ 4
#define SEGC_ (NIN_ / NSEG_)

#define KPAD  40   // bf16 smem row stride (conflict-free frag loads)

typedef unsigned long long ull;
typedef unsigned int u32;

// ---------------- f32x2 packed helpers ----------------
__device__ __forceinline__ ull pack2(float lo, float hi) {
    ull r; asm("mov.b64 %0,{%1,%2};" : "=l"(r) : "f"(lo), "f"(hi)); return r;
}
__device__ __forceinline__ void unpack2(float& lo, float& hi, ull v) {
    asm("mov.b64 {%0,%1},%2;" : "=f"(lo), "=f"(hi) : "l"(v));
}
__device__ __forceinline__ ull fma2(ull a, ull b, ull c) {
    ull d; asm("fma.rn.f32x2 %0,%1,%2,%3;" : "=l"(d) : "l"(a), "l"(b), "l"(c)); return d;
}
__device__ __forceinline__ ull mul2(ull a, ull b) {
    ull d; asm("mul.rn.f32x2 %0,%1,%2;" : "=l"(d) : "l"(a), "l"(b)); return d;
}
__device__ __forceinline__ ull add2(ull a, ull b) {
    ull d; asm("add.rn.f32x2 %0,%1,%2;" : "=l"(d) : "l"(a), "l"(b)); return d;
}

#define MMA16816(C, A, Bf)                                                   \
    asm volatile(                                                            \
        "mma.sync.aligned.m16n8k16.row.col.f32.bf16.bf16.f32 "               \
        "{%0,%1,%2,%3},{%4,%5,%6,%7},{%8,%9},{%0,%1,%2,%3};"                 \
        : "+f"((C)[0]), "+f"((C)[1]), "+f"((C)[2]), "+f"((C)[3])             \
        : "r"((A)[0]), "r"((A)[1]), "r"((A)[2]), "r"((A)[3]),                \
          "r"((Bf)[0]), "r"((Bf)[1]))

// ---------------- scratch ----------------
__device__ float          g_featT[B_ * NIN_ * COUT_];
__device__ float          g_pval[B_ * NSEG_ * M_ * 3];
__device__ int            g_pidx[B_ * NSEG_ * M_ * 3];
__device__ __nv_bfloat16  g_inhi[B_ * CIN_ * NIN_], g_inlo[B_ * CIN_ * NIN_];
__device__ __nv_bfloat16  g_y1hi[B_ * COUT_ * NIN_], g_y1lo[B_ * COUT_ * NIN_];
__device__ __nv_bfloat16  g_y2hi[B_ * COUT_ * NIN_], g_y2lo[B_ * COUT_ * NIN_];
__device__ __nv_bfloat16  g_w1hi[COUT_ * CIN_],  g_w1lo[COUT_ * CIN_];
__device__ __nv_bfloat16  g_w2hi[COUT_ * COUT_], g_w2lo[COUT_ * COUT_];
__device__ __nv_bfloat16  g_w3hi[COUT_ * COUT_], g_w3lo[COUT_ * COUT_];

// ---------------- fp32 -> bf16 hi/lo split ----------------
__global__ __launch_bounds__(256) void split_kernel(
    const float* __restrict__ src, __nv_bfloat16* __restrict__ hi,
    __nv_bfloat16* __restrict__ lo, int n)
{
    for (int i = blockIdx.x * 256 + threadIdx.x; i < n; i += gridDim.x * 256) {
        float v = src[i];
        __nv_bfloat16 h = __float2bfloat16(v);
        hi[i] = h;
        lo[i] = __float2bfloat16(v - __bfloat162float(h));
    }
}

// ---------------- tensor-core MLP layer: Conv1d(k=1)+BN+ReLU, bf16x3 ----------------
// Y[cout, n] = relu(sc[cout] * sum_k W[cout,k] X[k,n] + shf[cout])
// A = W (row major [m][k]), B = X (col of [k][n] -> staged transposed [n][k]).
// Block tile 128m x 64n, 8 warps = 4(m) x 2(n), warp tile 32x32, atoms 2x4.
__global__ __launch_bounds__(256) void mlp_mma_kernel(
    const __nv_bfloat16* __restrict__ Xhi, const __nv_bfloat16* __restrict__ Xlo,
    const __nv_bfloat16* __restrict__ Whi, const __nv_bfloat16* __restrict__ Wlo,
    const float* __restrict__ bias, const float* __restrict__ gamma,
    const float* __restrict__ betap, const float* __restrict__ rmean,
    const float* __restrict__ rvar,
    float* __restrict__ YT,                      // transposed fp32 out (featT)
    __nv_bfloat16* __restrict__ Yhi, __nv_bfloat16* __restrict__ Ylo,
    int K, int transposed)
{
    __shared__ __nv_bfloat16 WsH[COUT_][KPAD];
    __shared__ __nv_bfloat16 WsL[COUT_][KPAD];
    __shared__ __nv_bfloat16 XsH[64][KPAD];
    __shared__ __nv_bfloat16 XsL[64][KPAD];
    __shared__ float s_sc[COUT_], s_sh[COUT_];

    const int tid  = threadIdx.x;
    const int b    = blockIdx.y;
    const int n0   = blockIdx.x * 64;
    const int wid  = tid >> 5, lane = tid & 31;
    const int wm   = wid >> 1, wn = wid & 1;
    const int g    = lane >> 2, tig = lane & 3;

    if (tid < COUT_) {
        float s = gamma[tid] / sqrtf(rvar[tid] + 1e-5f);
        s_sc[tid] = s;
        s_sh[tid] = betap[tid] + (bias[tid] - rmean[tid]) * s;
    }

    float acc[2][4][4];
#pragma unroll
    for (int ma = 0; ma < 2; ma++)
#pragma unroll
        for (int na = 0; na < 4; na++)
#pragma unroll
            for (int r = 0; r < 4; r++) acc[ma][na][r] = 0.f;

    const __nv_bfloat16* XhiB = Xhi + (size_t)b * K * NIN_;
    const __nv_bfloat16* XloB = Xlo + (size_t)b * K * NIN_;

    for (int k0 = 0; k0 < K; k0 += 32) {
        // stage W [128 x 32] both splits (u32 = 2 bf16)
        for (int idx = tid; idx < COUT_ * 16; idx += 256) {
            int row = idx >> 4, cp = idx & 15;
            *(u32*)&WsH[row][2 * cp] = *(const u32*)(Whi + (size_t)row * K + k0 + 2 * cp);
            *(u32*)&WsL[row][2 * cp] = *(const u32*)(Wlo + (size_t)row * K + k0 + 2 * cp);
        }
        // stage X transposed: smem [n][k] from gmem [k][n]
        for (int idx = tid; idx < 32 * 32; idx += 256) {
            int kk = idx >> 5, np = idx & 31;
            u32 vh = *(const u32*)(XhiB + (size_t)(k0 + kk) * NIN_ + n0 + 2 * np);
            u32 vl = *(const u32*)(XloB + (size_t)(k0 + kk) * NIN_ + n0 + 2 * np);
            XsH[2 * np][kk]     = __ushort_as_bfloat16((unsigned short)(vh & 0xFFFF));
            XsH[2 * np + 1][kk] = __ushort_as_bfloat16((unsigned short)(vh >> 16));
            XsL[2 * np][kk]     = __ushort_as_bfloat16((unsigned short)(vl & 0xFFFF));
            XsL[2 * np + 1][kk] = __ushort_as_bfloat16((unsigned short)(vl >> 16));
        }
        __syncthreads();

#pragma unroll
        for (int ks = 0; ks < 2; ks++) {
            const int k16 = ks * 16;
            u32 aH[2][4], aL[2][4], bH[4][2], bL[4][2];
#pragma unroll
            for (int ma = 0; ma < 2; ma++) {
                int r0 = wm * 32 + ma * 16;
                aH[ma][0] = *(const u32*)&WsH[r0 + g][k16 + 2 * tig];
                aH[ma][1] = *(const u32*)&WsH[r0 + g + 8][k16 + 2 * tig];
                aH[ma][2] = *(const u32*)&WsH[r0 + g][k16 + 2 * tig + 8];
                aH[ma][3] = *(const u32*)&WsH[r0 + g + 8][k16 + 2 * tig + 8];
                aL[ma][0] = *(const u32*)&WsL[r0 + g][k16 + 2 * tig];
                aL[ma][1] = *(const u32*)&WsL[r0 + g + 8][k16 + 2 * tig];
                aL[ma][2] = *(const u32*)&WsL[r0 + g][k16 + 2 * tig + 8];
                aL[ma][3] = *(const u32*)&WsL[r0 + g + 8][k16 + 2 * tig + 8];
            }
#pragma unroll
            for (int na = 0; na < 4; na++) {
                int nb = wn * 32 + na * 8 + g;
                bH[na][0] = *(const u32*)&XsH[nb][k16 + 2 * tig];
                bH[na][1] = *(const u32*)&XsH[nb][k16 + 2 * tig + 8];
                bL[na][0] = *(const u32*)&XsL[nb][k16 + 2 * tig];
                bL[na][1] = *(const u32*)&XsL[nb][k16 + 2 * tig + 8];
            }
#pragma unroll
            for (int ma = 0; ma < 2; ma++)
#pragma unroll
                for (int na = 0; na < 4; na++) {
                    MMA16816(acc[ma][na], aH[ma], bH[na]);
                    MMA16816(acc[ma][na], aH[ma], bL[na]);
                    MMA16816(acc[ma][na], aL[ma], bH[na]);
                }
        }
        __syncthreads();
    }

    // epilogue: BN + ReLU, then write
#pragma unroll
    for (int ma = 0; ma < 2; ma++) {
        int r0 = wm * 32 + ma * 16 + g;
        int r1 = r0 + 8;
        float sc0 = s_sc[r0], sh0 = s_sh[r0];
        float sc1 = s_sc[r1], sh1 = s_sh[r1];
#pragma unroll
        for (int na = 0; na < 4; na++) {
            int n = n0 + wn * 32 + na * 8 + 2 * tig;
            float v00 = fmaxf(__fmaf_rn(acc[ma][na][0], sc0, sh0), 0.f); // (r0, n)
            float v01 = fmaxf(__fmaf_rn(acc[ma][na][1], sc0, sh0), 0.f); // (r0, n+1)
            float v10 = fmaxf(__fmaf_rn(acc[ma][na][2], sc1, sh1), 0.f); // (r1, n)
            float v11 = fmaxf(__fmaf_rn(acc[ma][na][3], sc1, sh1), 0.f); // (r1, n+1)
            if (transposed) {
                float* base = YT + (size_t)b * NIN_ * COUT_;
                base[(size_t)(n)     * COUT_ + r0] = v00;
                base[(size_t)(n + 1) * COUT_ + r0] = v01;
                base[(size_t)(n)     * COUT_ + r1] = v10;
                base[(size_t)(n + 1) * COUT_ + r1] = v11;
            } else {
                // split and write packed pairs (n, n+1)
                __nv_bfloat16 h00 = __float2bfloat16(v00);
                __nv_bfloat16 h01 = __float2bfloat16(v01);
                __nv_bfloat16 h10 = __float2bfloat16(v10);
                __nv_bfloat16 h11 = __float2bfloat16(v11);
                u32 ph0 = (u32)__bfloat16_as_ushort(h00) |
                          ((u32)__bfloat16_as_ushort(h01) << 16);
                u32 ph1 = (u32)__bfloat16_as_ushort(h10) |
                          ((u32)__bfloat16_as_ushort(h11) << 16);
                u32 pl0 = (u32)__bfloat16_as_ushort(__float2bfloat16(v00 - __bfloat162float(h00))) |
                          ((u32)__bfloat16_as_ushort(__float2bfloat16(v01 - __bfloat162float(h01))) << 16);
                u32 pl1 = (u32)__bfloat16_as_ushort(__float2bfloat16(v10 - __bfloat162float(h10))) |
                          ((u32)__bfloat16_as_ushort(__float2bfloat16(v11 - __bfloat162float(h11))) << 16);
                *(u32*)(Yhi + ((size_t)b * COUT_ + r0) * NIN_ + n) = ph0;
                *(u32*)(Yhi + ((size_t)b * COUT_ + r1) * NIN_ + n) = ph1;
                *(u32*)(Ylo + ((size_t)b * COUT_ + r0) * NIN_ + n) = pl0;
                *(u32*)(Ylo + ((size_t)b * COUT_ + r1) * NIN_ + n) = pl1;
            }
        }
    }
}

// ---------------- segmented exact top-3 scan (R9/R4 proven version) ----------------
#define INSERT3(d_, j_, s0_, s1_, s2_, i0_, i1_, i2_)                      \
    if (d_ < s2_) {                                                        \
        if (d_ < s1_) {                                                    \
            s2_ = s1_; i2_ = i1_;                                          \
            if (d_ < s0_) { s1_ = s0_; i1_ = i0_; s0_ = d_; i0_ = j_; }    \
            else          { s1_ = d_;  i1_ = j_; }                         \
        } else { s2_ = d_; i2_ = j_; }                                     \
    }

__global__ __launch_bounds__(256) void scan_kernel(
    const float* __restrict__ xyzin, const float* __restrict__ xyzout,
    float* __restrict__ pval, int* __restrict__ pidx)
{
    __shared__ __align__(16) float xs[SEGC_];
    __shared__ __align__(16) float ys[SEGC_];
    __shared__ __align__(16) float zs[SEGC_];
    __shared__ __align__(16) float ss[SEGC_];

    const int tid = threadIdx.x;
    const int seg = blockIdx.y;
    const int b   = blockIdx.z;
    const int jbase = seg * SEGC_;
    const float* pin = xyzin + ((size_t)b * NIN_ + jbase) * 3;

    for (int j = tid; j < SEGC_; j += 256) {
        float x = pin[j * 3 + 0];
        float y = pin[j * 3 + 1];
        float z = pin[j * 3 + 2];
        xs[j] = x; ys[j] = y; zs[j] = z;
        ss[j] = __fadd_rn(__fadd_rn(__fmul_rn(x, x), __fmul_rn(y, y)),
                          __fmul_rn(z, z));
    }
    __syncthreads();

    const int m0 = blockIdx.x * 512 + tid;
    const int m1 = m0 + 256;

    const float* q0 = xyzout + ((size_t)b * M_ + m0) * 3;
    const float* q1 = xyzout + ((size_t)b * M_ + m1) * 3;
    float q0x = q0[0], q0y = q0[1], q0z = q0[2];
    float q1x = q1[0], q1y = q1[1], q1z = q1[2];
    float q0n = __fadd_rn(__fadd_rn(__fmul_rn(q0x, q0x), __fmul_rn(q0y, q0y)),
                          __fmul_rn(q0z, q0z));
    float q1n = __fadd_rn(__fadd_rn(__fmul_rn(q1x, q1x), __fmul_rn(q1y, q1y)),
                          __fmul_rn(q1z, q1z));

    const ull qx20 = pack2(q0x, q0x), qy20 = pack2(q0y, q0y);
    const ull qz20 = pack2(q0z, q0z), qn20 = pack2(q0n, q0n);
    const ull qx21 = pack2(q1x, q1x), qy21 = pack2(q1y, q1y);
    const ull qz21 = pack2(q1z, q1z), qn21 = pack2(q1n, q1n);
    const ull n22  = pack2(-2.0f, -2.0f);

    float a_s0 = FLT_MAX, a_s1 = FLT_MAX, a_s2 = FLT_MAX;
    float b_s0 = FLT_MAX, b_s1 = FLT_MAX, b_s2 = FLT_MAX;
    int a_i0 = 0, a_i1 = 0, a_i2 = 0;
    int b_i0 = 0, b_i1 = 0, b_i2 = 0;

    const ulonglong2* xs4 = (const ulonglong2*)xs;
    const ulonglong2* ys4 = (const ulonglong2*)ys;
    const ulonglong2* zs4 = (const ulonglong2*)zs;
    const ulonglong2* ss4 = (const ulonglong2*)ss;

#pragma unroll 2
    for (int jq = 0; jq < SEGC_ / 4; jq++) {
        ulonglong2 xq = xs4[jq], yq = ys4[jq], zq = zs4[jq], sq = ss4[jq];
#pragma unroll
        for (int p = 0; p < 2; p++) {
            ull xp = p ? xq.y : xq.x;
            ull yp = p ? yq.y : yq.x;
            ull zp = p ? zq.y : zq.x;
            ull sp = p ? sq.y : sq.x;
            int j = jbase + 4 * jq + 2 * p;
            {
                ull dot = fma2(qz20, zp, fma2(qy20, yp, mul2(qx20, xp)));
                ull d2  = fma2(n22, dot, add2(qn20, sp));
                float dlo, dhi; unpack2(dlo, dhi, d2);
                if (__builtin_expect(fminf(dlo, dhi) < a_s2, 0)) {
                    float cl = (dlo < 0.0f) ? 1e-7f : dlo;
                    float ch = (dhi < 0.0f) ? 1e-7f : dhi;
                    INSERT3(cl, j,     a_s0, a_s1, a_s2, a_i0, a_i1, a_i2);
                    INSERT3(ch, j + 1, a_s0, a_s1, a_s2, a_i0, a_i1, a_i2);
                }
            }
            {
                ull dot = fma2(qz21, zp, fma2(qy21, yp, mul2(qx21, xp)));
                ull d2  = fma2(n22, dot, add2(qn21, sp));
                float dlo, dhi; unpack2(dlo, dhi, d2);
                if (__builtin_expect(fminf(dlo, dhi) < b_s2, 0)) {
                    float cl = (dlo < 0.0f) ? 1e-7f : dlo;
                    float ch = (dhi < 0.0f) ? 1e-7f : dhi;
                    INSERT3(cl, j,     b_s0, b_s1, b_s2, b_i0, b_i1, b_i2);
                    INSERT3(ch, j + 1, b_s0, b_s1, b_s2, b_i0, b_i1, b_i2);
                }
            }
        }
    }

    {
        size_t o = (((size_t)b * NSEG_ + seg) * M_ + m0) * 3;
        pval[o + 0] = a_s0; pval[o + 1] = a_s1; pval[o + 2] = a_s2;
        pidx[o + 0] = a_i0; pidx[o + 1] = a_i1; pidx[o + 2] = a_i2;
    }
    {
        size_t o = (((size_t)b * NSEG_ + seg) * M_ + m1) * 3;
        pval[o + 0] = b_s0; pval[o + 1] = b_s1; pval[o + 2] = b_s2;
        pidx[o + 0] = b_i0; pidx[o + 1] = b_i1; pidx[o + 2] = b_i2;
    }
}

// ---------------- fused merge + gather + weighted interpolation ----------------
__global__ __launch_bounds__(128) void interp_kernel(
    const float* __restrict__ featT,
    const float* __restrict__ pval, const int* __restrict__ pidx,
    float* __restrict__ out)
{
    __shared__ float sacc[64][COUT_ + 1];
    __shared__ float sw[64 * 3];
    __shared__ int   si[64 * 3];
    const int tid = threadIdx.x;
    const int b   = blockIdx.y;
    const int m0  = blockIdx.x * 64;

    if (tid < 64) {
        const int m = m0 + tid;
        float v[NSEG_ * 3];
        int   ix[NSEG_ * 3];
#pragma unroll
        for (int s = 0; s < NSEG_; s++) {
            size_t o = (((size_t)b * NSEG_ + s) * M_ + m) * 3;
#pragma unroll
            for (int k = 0; k < 3; k++) {
                v[s * 3 + k]  = pval[o + k];
                ix[s * 3 + k] = pidx[o + k];
            }
        }
        float rs[3]; int ri[3];
#pragma unroll
        for (int k = 0; k < 3; k++) {
            int best = 0;
#pragma unroll
            for (int t = 1; t < NSEG_ * 3; t++) {
                bool better = (v[t] < v[best]) ||
                              (v[t] == v[best] && ix[t] < ix[best]);
                if (better) best = t;
            }
            rs[k] = v[best]; ri[k] = ix[best];
            v[best] = FLT_MAX; ix[best] = 0x7FFFFFFF;
        }
        float w0 = __fdiv_rn(1.0f, rs[0]);
        float w1 = __fdiv_rn(1.0f, rs[1]);
        float w2 = __fdiv_rn(1.0f, rs[2]);
        float wsum = __fadd_rn(__fadd_rn(w0, w1), w2);
        sw[tid * 3 + 0] = __fdiv_rn(w0, wsum);
        sw[tid * 3 + 1] = __fdiv_rn(w1, wsum);
        sw[tid * 3 + 2] = __fdiv_rn(w2, wsum);
        si[tid * 3 + 0] = ri[0];
        si[tid * 3 + 1] = ri[1];
        si[tid * 3 + 2] = ri[2];
    }
    __syncthreads();

    const float* fb = featT + (size_t)b * NIN_ * COUT_;
    const int c = tid;
#pragma unroll 2
    for (int qq = 0; qq < 64; qq++) {
        float w0 = sw[qq * 3], w1 = sw[qq * 3 + 1], w2 = sw[qq * 3 + 2];
        const float* f0 = fb + (size_t)si[qq * 3]     * COUT_;
        const float* f1 = fb + (size_t)si[qq * 3 + 1] * COUT_;
        const float* f2 = fb + (size_t)si[qq * 3 + 2] * COUT_;
        sacc[qq][c] = __fmaf_rn(w2, f2[c],
                      __fmaf_rn(w1, f1[c], __fmul_rn(w0, f0[c])));
    }
    __syncthreads();

#pragma unroll
    for (int cc = 0; cc < COUT_; cc += 2) {
        int ci = cc + (tid >> 6);
        int mi = tid & 63;
        out[((size_t)b * COUT_ + ci) * M_ + m0 + mi] = sacc[mi][ci];
    }
}

// ---------------- launch (stream-forked: scan || split+MLP chain) ----------------
extern "C" void kernel_launch(void* const* d_in, const int* in_sizes, int n_in,
                              void* d_out, int out_size)
{
    (void)in_sizes; (void)n_in; (void)out_size;
    const float* rgb    = (const float*)d_in[0];
    const float* xyzin  = (const float*)d_in[1];
    const float* xyzout = (const float*)d_in[2];
    const float* w1 = (const float*)d_in[3];
    const float* b1 = (const float*)d_in[4];
    const float* g1 = (const float*)d_in[5];
    const float* be1 = (const float*)d_in[6];
    const float* rm1 = (const float*)d_in[7];
    const float* rv1 = (const float*)d_in[8];
    const float* w2 = (const float*)d_in[9];
    const float* b2 = (const float*)d_in[10];
    const float* g2 = (const float*)d_in[11];
    const float* be2 = (const float*)d_in[12];
    const float* rm2 = (const float*)d_in[13];
    const float* rv2 = (const float*)d_in[14];
    const float* w3 = (const float*)d_in[15];
    const float* b3 = (const float*)d_in[16];
    const float* g3 = (const float*)d_in[17];
    const float* be3 = (const float*)d_in[18];
    const float* rm3 = (const float*)d_in[19];
    const float* rv3 = (const float*)d_in[20];
    float* out = (float*)d_out;

    float *featT, *pvp;
    int *pip;
    __nv_bfloat16 *inhi, *inlo, *y1hi, *y1lo, *y2hi, *y2lo;
    __nv_bfloat16 *w1hi, *w1lo, *w2hi, *w2lo, *w3hi, *w3lo;
    cudaGetSymbolAddress((void**)&featT, g_featT);
    cudaGetSymbolAddress((void**)&pvp,   g_pval);
    cudaGetSymbolAddress((void**)&pip,   g_pidx);
    cudaGetSymbolAddress((void**)&inhi,  g_inhi);
    cudaGetSymbolAddress((void**)&inlo,  g_inlo);
    cudaGetSymbolAddress((void**)&y1hi,  g_y1hi);
    cudaGetSymbolAddress((void**)&y1lo,  g_y1lo);
    cudaGetSymbolAddress((void**)&y2hi,  g_y2hi);
    cudaGetSymbolAddress((void**)&y2lo,  g_y2lo);
    cudaGetSymbolAddress((void**)&w1hi,  g_w1hi);
    cudaGetSymbolAddress((void**)&w1lo,  g_w1lo);
    cudaGetSymbolAddress((void**)&w2hi,  g_w2hi);
    cudaGetSymbolAddress((void**)&w2lo,  g_w2lo);
    cudaGetSymbolAddress((void**)&w3hi,  g_w3hi);
    cudaGetSymbolAddress((void**)&w3lo,  g_w3lo);

    static cudaStream_t s_side = nullptr;
    static cudaEvent_t  ev_fork = nullptr, ev_join = nullptr;
    if (s_side == nullptr) {
        cudaStreamCreateWithFlags(&s_side, cudaStreamNonBlocking);
        cudaEventCreateWithFlags(&ev_fork, cudaEventDisableTiming);
        cudaEventCreateWithFlags(&ev_join, cudaEventDisableTiming);
    }

    cudaEventRecord(ev_fork, 0);
    cudaStreamWaitEvent(s_side, ev_fork, 0);

    // side stream: 3-NN scan (unchanged from R9)
    dim3 scan_grid(M_ / 512, NSEG_, B_);
    scan_kernel<<<scan_grid, 256, 0, s_side>>>(xyzin, xyzout, pvp, pip);
    cudaEventRecord(ev_join, s_side);

    // default stream: splits + tensor-core MLP chain (runs under scan)
    split_kernel<<<256, 256>>>(rgb, inhi, inlo, B_ * CIN_ * NIN_);
    split_kernel<<<32, 256>>>(w1, w1hi, w1lo, COUT_ * CIN_);
    split_kernel<<<16, 256>>>(w2, w2hi, w2lo, COUT_ * COUT_);
    split_kernel<<<16, 256>>>(w3, w3hi, w3lo, COUT_ * COUT_);

    dim3 gemm_grid(NIN_ / 64, B_);
    mlp_mma_kernel<<<gemm_grid, 256>>>(inhi, inlo, w1hi, w1lo,
                                       b1, g1, be1, rm1, rv1,
                                       nullptr, y1hi, y1lo, CIN_, 0);
    mlp_mma_kernel<<<gemm_grid, 256>>>(y1hi, y1lo, w2hi, w2lo,
                                       b2, g2, be2, rm2, rv2,
                                       nullptr, y2hi, y2lo, COUT_, 0);
    mlp_mma_kernel<<<gemm_grid, 256>>>(y2hi, y2lo, w3hi, w3lo,
                                       b3, g3, be3, rm3, rv3,
                                       featT, nullptr, nullptr, COUT_, 1);

    cudaStreamWaitEvent(0, ev_join, 0);

    dim3 interp_grid(M_ / 64, B_);
    interp_kernel<<<interp_grid, 128>>>(featT, pvp, pip, out);
}

// round 12
// speedup vs baseline: 1.2517x; 1.2075x over previous
#include <cuda_runtime.h>
#include <cuda_bf16.h>
#include <math.h>
#include <float.h>
#include <stdint.h>

#define B_    4
#define NIN_  4096
#define M_    16384
#define CIN_  256
#define COUT_ 128
#define NSEG_ 4
#define SEGC_ (NIN_ / NSEG_)

#define KPAD  40   // bf16 smem row stride (conflict-free frag loads)

typedef unsigned long long ull;
typedef unsigned int u32;

// ---------------- f32x2 packed helpers ----------------
__device__ __forceinline__ ull pack2(float lo, float hi) {
    ull r; asm("mov.b64 %0,{%1,%2};" : "=l"(r) : "f"(lo), "f"(hi)); return r;
}
__device__ __forceinline__ void unpack2(float& lo, float& hi, ull v) {
    asm("mov.b64 {%0,%1},%2;" : "=f"(lo), "=f"(hi) : "l"(v));
}
__device__ __forceinline__ ull fma2(ull a, ull b, ull c) {
    ull d; asm("fma.rn.f32x2 %0,%1,%2,%3;" : "=l"(d) : "l"(a), "l"(b), "l"(c)); return d;
}
__device__ __forceinline__ ull mul2(ull a, ull b) {
    ull d; asm("mul.rn.f32x2 %0,%1,%2;" : "=l"(d) : "l"(a), "l"(b)); return d;
}
__device__ __forceinline__ ull add2(ull a, ull b) {
    ull d; asm("add.rn.f32x2 %0,%1,%2;" : "=l"(d) : "l"(a), "l"(b)); return d;
}

#define MMA16816(C, A, Bf)                                                   \
    asm volatile(                                                            \
        "mma.sync.aligned.m16n8k16.row.col.f32.bf16.bf16.f32 "               \
        "{%0,%1,%2,%3},{%4,%5,%6,%7},{%8,%9},{%0,%1,%2,%3};"                 \
        : "+f"((C)[0]), "+f"((C)[1]), "+f"((C)[2]), "+f"((C)[3])             \
        : "r"((A)[0]), "r"((A)[1]), "r"((A)[2]), "r"((A)[3]),                \
          "r"((Bf)[0]), "r"((Bf)[1]))

__device__ __forceinline__ u32 split_pack_hi(float a, float b,
                                             __nv_bfloat16& ha, __nv_bfloat16& hb) {
    ha = __float2bfloat16(a);
    hb = __float2bfloat16(b);
    return (u32)__bfloat16_as_ushort(ha) | ((u32)__bfloat16_as_ushort(hb) << 16);
}
__device__ __forceinline__ u32 pack_lo(float a, float b,
                                       __nv_bfloat16 ha, __nv_bfloat16 hb) {
    __nv_bfloat16 la = __float2bfloat16(a - __bfloat162float(ha));
    __nv_bfloat16 lb = __float2bfloat16(b - __bfloat162float(hb));
    return (u32)__bfloat16_as_ushort(la) | ((u32)__bfloat16_as_ushort(lb) << 16);
}

// ---------------- scratch ----------------
__device__ float g_act1[B_ * NIN_ * COUT_];   // layer outputs, [n][cout] fp32
__device__ float g_act2[B_ * NIN_ * COUT_];
__device__ float g_featT[B_ * NIN_ * COUT_];
__device__ float g_pval[B_ * NSEG_ * M_ * 3];
__device__ int   g_pidx[B_ * NSEG_ * M_ * 3];

// ---------------- tensor-core MLP layer (fp32 in/out, in-kernel bf16x3 split) ----------------
// Y[n][cout] = relu(sc[cout] * sum_k W[cout,k] X[k,n] + shf[cout])
// xmode 0: X is [n][k] fp32 (activations);  xmode 1: X is [k][n] fp32 (rgb).
// Block tile 128m x 64n, 8 warps = 4(m) x 2(n); frag mapping identical to R11 (verified).
__global__ __launch_bounds__(256) void mlp_mma_kernel(
    const float* __restrict__ X, const float* __restrict__ W,
    const float* __restrict__ bias, const float* __restrict__ gamma,
    const float* __restrict__ betap, const float* __restrict__ rmean,
    const float* __restrict__ rvar,
    float* __restrict__ Y, int K, int xmode)
{
    __shared__ __nv_bfloat16 WsH[COUT_][KPAD];
    __shared__ __nv_bfloat16 WsL[COUT_][KPAD];
    __shared__ __nv_bfloat16 XsH[64][KPAD];
    __shared__ __nv_bfloat16 XsL[64][KPAD];
    __shared__ float s_sc[COUT_], s_sh[COUT_];

    const int tid  = threadIdx.x;
    const int b    = blockIdx.y;
    const int n0   = blockIdx.x * 64;
    const int wid  = tid >> 5, lane = tid & 31;
    const int wm   = wid >> 1, wn = wid & 1;
    const int g    = lane >> 2, tig = lane & 3;

    if (tid < COUT_) {
        float s = gamma[tid] / sqrtf(rvar[tid] + 1e-5f);
        s_sc[tid] = s;
        s_sh[tid] = betap[tid] + (bias[tid] - rmean[tid]) * s;
    }

    float acc[2][4][4];
#pragma unroll
    for (int ma = 0; ma < 2; ma++)
#pragma unroll
        for (int na = 0; na < 4; na++)
#pragma unroll
            for (int r = 0; r < 4; r++) acc[ma][na][r] = 0.f;

    const float* Xb = X + (size_t)b * K * NIN_;   // same element count both modes

    for (int k0 = 0; k0 < K; k0 += 32) {
        // stage W [128 x 32]: fp32 -> hi/lo bf16 split in-register
        for (int idx = tid; idx < COUT_ * 16; idx += 256) {
            int row = idx >> 4, cp = idx & 15;
            float2 v = *(const float2*)(W + (size_t)row * K + k0 + 2 * cp);
            __nv_bfloat16 h0, h1;
            *(u32*)&WsH[row][2 * cp] = split_pack_hi(v.x, v.y, h0, h1);
            *(u32*)&WsL[row][2 * cp] = pack_lo(v.x, v.y, h0, h1);
        }
        // stage X [64 n x 32 k]
        if (xmode == 0) {
            // X[n][k]: k contiguous -> float2, direct u32 packing
            for (int idx = tid; idx < 64 * 16; idx += 256) {
                int row = idx >> 4, cp = idx & 15;
                float2 v = *(const float2*)(Xb + (size_t)(n0 + row) * K + k0 + 2 * cp);
                __nv_bfloat16 h0, h1;
                *(u32*)&XsH[row][2 * cp] = split_pack_hi(v.x, v.y, h0, h1);
                *(u32*)&XsL[row][2 * cp] = pack_lo(v.x, v.y, h0, h1);
            }
        } else {
            // X[k][n] (rgb): coalesced reads, scalar transposed smem stores
            for (int idx = tid; idx < 32 * 64; idx += 256) {
                int kk = idx >> 6, nn = idx & 63;
                float v = Xb[(size_t)(k0 + kk) * NIN_ + n0 + nn];
                __nv_bfloat16 h = __float2bfloat16(v);
                XsH[nn][kk] = h;
                XsL[nn][kk] = __float2bfloat16(v - __bfloat162float(h));
            }
        }
        __syncthreads();

#pragma unroll
        for (int ks = 0; ks < 2; ks++) {
            const int k16 = ks * 16;
            u32 aH[2][4], aL[2][4], bH[4][2], bL[4][2];
#pragma unroll
            for (int ma = 0; ma < 2; ma++) {
                int r0 = wm * 32 + ma * 16;
                aH[ma][0] = *(const u32*)&WsH[r0 + g][k16 + 2 * tig];
                aH[ma][1] = *(const u32*)&WsH[r0 + g + 8][k16 + 2 * tig];
                aH[ma][2] = *(const u32*)&WsH[r0 + g][k16 + 2 * tig + 8];
                aH[ma][3] = *(const u32*)&WsH[r0 + g + 8][k16 + 2 * tig + 8];
                aL[ma][0] = *(const u32*)&WsL[r0 + g][k16 + 2 * tig];
                aL[ma][1] = *(const u32*)&WsL[r0 + g + 8][k16 + 2 * tig];
                aL[ma][2] = *(const u32*)&WsL[r0 + g][k16 + 2 * tig + 8];
                aL[ma][3] = *(const u32*)&WsL[r0 + g + 8][k16 + 2 * tig + 8];
            }
#pragma unroll
            for (int na = 0; na < 4; na++) {
                int nb = wn * 32 + na * 8 + g;
                bH[na][0] = *(const u32*)&XsH[nb][k16 + 2 * tig];
                bH[na][1] = *(const u32*)&XsH[nb][k16 + 2 * tig + 8];
                bL[na][0] = *(const u32*)&XsL[nb][k16 + 2 * tig];
                bL[na][1] = *(const u32*)&XsL[nb][k16 + 2 * tig + 8];
            }
#pragma unroll
            for (int ma = 0; ma < 2; ma++)
#pragma unroll
                for (int na = 0; na < 4; na++) {
                    MMA16816(acc[ma][na], aH[ma], bH[na]);
                    MMA16816(acc[ma][na], aH[ma], bL[na]);
                    MMA16816(acc[ma][na], aL[ma], bH[na]);
                }
        }
        __syncthreads();
    }

    // epilogue: BN + ReLU, write fp32 [n][cout] (R11 transposed path, verified)
    float* base = Y + (size_t)b * NIN_ * COUT_;
#pragma unroll
    for (int ma = 0; ma < 2; ma++) {
        int r0 = wm * 32 + ma * 16 + g;
        int r1 = r0 + 8;
        float sc0 = s_sc[r0], sh0 = s_sh[r0];
        float sc1 = s_sc[r1], sh1 = s_sh[r1];
#pragma unroll
        for (int na = 0; na < 4; na++) {
            int n = n0 + wn * 32 + na * 8 + 2 * tig;
            base[(size_t)(n)     * COUT_ + r0] = fmaxf(__fmaf_rn(acc[ma][na][0], sc0, sh0), 0.f);
            base[(size_t)(n + 1) * COUT_ + r0] = fmaxf(__fmaf_rn(acc[ma][na][1], sc0, sh0), 0.f);
            base[(size_t)(n)     * COUT_ + r1] = fmaxf(__fmaf_rn(acc[ma][na][2], sc1, sh1), 0.f);
            base[(size_t)(n + 1) * COUT_ + r1] = fmaxf(__fmaf_rn(acc[ma][na][3], sc1, sh1), 0.f);
        }
    }
}

// ---------------- segmented exact top-3 scan (R9/R4 proven version) ----------------
#define INSERT3(d_, j_, s0_, s1_, s2_, i0_, i1_, i2_)                      \
    if (d_ < s2_) {                                                        \
        if (d_ < s1_) {                                                    \
            s2_ = s1_; i2_ = i1_;                                          \
            if (d_ < s0_) { s1_ = s0_; i1_ = i0_; s0_ = d_; i0_ = j_; }    \
            else          { s1_ = d_;  i1_ = j_; }                         \
        } else { s2_ = d_; i2_ = j_; }                                     \
    }

__global__ __launch_bounds__(256) void scan_kernel(
    const float* __restrict__ xyzin, const float* __restrict__ xyzout,
    float* __restrict__ pval, int* __restrict__ pidx)
{
    __shared__ __align__(16) float xs[SEGC_];
    __shared__ __align__(16) float ys[SEGC_];
    __shared__ __align__(16) float zs[SEGC_];
    __shared__ __align__(16) float ss[SEGC_];

    const int tid = threadIdx.x;
    const int seg = blockIdx.y;
    const int b   = blockIdx.z;
    const int jbase = seg * SEGC_;
    const float* pin = xyzin + ((size_t)b * NIN_ + jbase) * 3;

    for (int j = tid; j < SEGC_; j += 256) {
        float x = pin[j * 3 + 0];
        float y = pin[j * 3 + 1];
        float z = pin[j * 3 + 2];
        xs[j] = x; ys[j] = y; zs[j] = z;
        ss[j] = __fadd_rn(__fadd_rn(__fmul_rn(x, x), __fmul_rn(y, y)),
                          __fmul_rn(z, z));
    }
    __syncthreads();

    const int m0 = blockIdx.x * 512 + tid;
    const int m1 = m0 + 256;

    const float* q0 = xyzout + ((size_t)b * M_ + m0) * 3;
    const float* q1 = xyzout + ((size_t)b * M_ + m1) * 3;
    float q0x = q0[0], q0y = q0[1], q0z = q0[2];
    float q1x = q1[0], q1y = q1[1], q1z = q1[2];
    float q0n = __fadd_rn(__fadd_rn(__fmul_rn(q0x, q0x), __fmul_rn(q0y, q0y)),
                          __fmul_rn(q0z, q0z));
    float q1n = __fadd_rn(__fadd_rn(__fmul_rn(q1x, q1x), __fmul_rn(q1y, q1y)),
                          __fmul_rn(q1z, q1z));

    const ull qx20 = pack2(q0x, q0x), qy20 = pack2(q0y, q0y);
    const ull qz20 = pack2(q0z, q0z), qn20 = pack2(q0n, q0n);
    const ull qx21 = pack2(q1x, q1x), qy21 = pack2(q1y, q1y);
    const ull qz21 = pack2(q1z, q1z), qn21 = pack2(q1n, q1n);
    const ull n22  = pack2(-2.0f, -2.0f);

    float a_s0 = FLT_MAX, a_s1 = FLT_MAX, a_s2 = FLT_MAX;
    float b_s0 = FLT_MAX, b_s1 = FLT_MAX, b_s2 = FLT_MAX;
    int a_i0 = 0, a_i1 = 0, a_i2 = 0;
    int b_i0 = 0, b_i1 = 0, b_i2 = 0;

    const ulonglong2* xs4 = (const ulonglong2*)xs;
    const ulonglong2* ys4 = (const ulonglong2*)ys;
    const ulonglong2* zs4 = (const ulonglong2*)zs;
    const ulonglong2* ss4 = (const ulonglong2*)ss;

#pragma unroll 2
    for (int jq = 0; jq < SEGC_ / 4; jq++) {
        ulonglong2 xq = xs4[jq], yq = ys4[jq], zq = zs4[jq], sq = ss4[jq];
#pragma unroll
        for (int p = 0; p < 2; p++) {
            ull xp = p ? xq.y : xq.x;
            ull yp = p ? yq.y : yq.x;
            ull zp = p ? zq.y : zq.x;
            ull sp = p ? sq.y : sq.x;
            int j = jbase + 4 * jq + 2 * p;
            {
                ull dot = fma2(qz20, zp, fma2(qy20, yp, mul2(qx20, xp)));
                ull d2  = fma2(n22, dot, add2(qn20, sp));
                float dlo, dhi; unpack2(dlo, dhi, d2);
                if (__builtin_expect(fminf(dlo, dhi) < a_s2, 0)) {
                    float cl = (dlo < 0.0f) ? 1e-7f : dlo;
                    float ch = (dhi < 0.0f) ? 1e-7f : dhi;
                    INSERT3(cl, j,     a_s0, a_s1, a_s2, a_i0, a_i1, a_i2);
                    INSERT3(ch, j + 1, a_s0, a_s1, a_s2, a_i0, a_i1, a_i2);
                }
            }
            {
                ull dot = fma2(qz21, zp, fma2(qy21, yp, mul2(qx21, xp)));
                ull d2  = fma2(n22, dot, add2(qn21, sp));
                float dlo, dhi; unpack2(dlo, dhi, d2);
                if (__builtin_expect(fminf(dlo, dhi) < b_s2, 0)) {
                    float cl = (dlo < 0.0f) ? 1e-7f : dlo;
                    float ch = (dhi < 0.0f) ? 1e-7f : dhi;
                    INSERT3(cl, j,     b_s0, b_s1, b_s2, b_i0, b_i1, b_i2);
                    INSERT3(ch, j + 1, b_s0, b_s1, b_s2, b_i0, b_i1, b_i2);
                }
            }
        }
    }

    {
        size_t o = (((size_t)b * NSEG_ + seg) * M_ + m0) * 3;
        pval[o + 0] = a_s0; pval[o + 1] = a_s1; pval[o + 2] = a_s2;
        pidx[o + 0] = a_i0; pidx[o + 1] = a_i1; pidx[o + 2] = a_i2;
    }
    {
        size_t o = (((size_t)b * NSEG_ + seg) * M_ + m1) * 3;
        pval[o + 0] = b_s0; pval[o + 1] = b_s1; pval[o + 2] = b_s2;
        pidx[o + 0] = b_i0; pidx[o + 1] = b_i1; pidx[o + 2] = b_i2;
    }
}

// ---------------- fused merge + gather + weighted interpolation ----------------
__global__ __launch_bounds__(128) void interp_kernel(
    const float* __restrict__ featT,
    const float* __restrict__ pval, const int* __restrict__ pidx,
    float* __restrict__ out)
{
    __shared__ float sacc[64][COUT_ + 1];
    __shared__ float sw[64 * 3];
    __shared__ int   si[64 * 3];
    const int tid = threadIdx.x;
    const int b   = blockIdx.y;
    const int m0  = blockIdx.x * 64;

    if (tid < 64) {
        const int m = m0 + tid;
        float v[NSEG_ * 3];
        int   ix[NSEG_ * 3];
#pragma unroll
        for (int s = 0; s < NSEG_; s++) {
            size_t o = (((size_t)b * NSEG_ + s) * M_ + m) * 3;
#pragma unroll
            for (int k = 0; k < 3; k++) {
                v[s * 3 + k]  = pval[o + k];
                ix[s * 3 + k] = pidx[o + k];
            }
        }
        float rs[3]; int ri[3];
#pragma unroll
        for (int k = 0; k < 3; k++) {
            int best = 0;
#pragma unroll
            for (int t = 1; t < NSEG_ * 3; t++) {
                bool better = (v[t] < v[best]) ||
                              (v[t] == v[best] && ix[t] < ix[best]);
                if (better) best = t;
            }
            rs[k] = v[best]; ri[k] = ix[best];
            v[best] = FLT_MAX; ix[best] = 0x7FFFFFFF;
        }
        float w0 = __fdiv_rn(1.0f, rs[0]);
        float w1 = __fdiv_rn(1.0f, rs[1]);
        float w2 = __fdiv_rn(1.0f, rs[2]);
        float wsum = __fadd_rn(__fadd_rn(w0, w1), w2);
        sw[tid * 3 + 0] = __fdiv_rn(w0, wsum);
        sw[tid * 3 + 1] = __fdiv_rn(w1, wsum);
        sw[tid * 3 + 2] = __fdiv_rn(w2, wsum);
        si[tid * 3 + 0] = ri[0];
        si[tid * 3 + 1] = ri[1];
        si[tid * 3 + 2] = ri[2];
    }
    __syncthreads();

    const float* fb = featT + (size_t)b * NIN_ * COUT_;
    const int c = tid;
#pragma unroll 2
    for (int qq = 0; qq < 64; qq++) {
        float w0 = sw[qq * 3], w1 = sw[qq * 3 + 1], w2 = sw[qq * 3 + 2];
        const float* f0 = fb + (size_t)si[qq * 3]     * COUT_;
        const float* f1 = fb + (size_t)si[qq * 3 + 1] * COUT_;
        const float* f2 = fb + (size_t)si[qq * 3 + 2] * COUT_;
        sacc[qq][c] = __fmaf_rn(w2, f2[c],
                      __fmaf_rn(w1, f1[c], __fmul_rn(w0, f0[c])));
    }
    __syncthreads();

#pragma unroll
    for (int cc = 0; cc < COUT_; cc += 2) {
        int ci = cc + (tid >> 6);
        int mi = tid & 63;
        out[((size_t)b * COUT_ + ci) * M_ + m0 + mi] = sacc[mi][ci];
    }
}

// ---------------- launch (stream-forked: scan || MLP chain) ----------------
extern "C" void kernel_launch(void* const* d_in, const int* in_sizes, int n_in,
                              void* d_out, int out_size)
{
    (void)in_sizes; (void)n_in; (void)out_size;
    const float* rgb    = (const float*)d_in[0];
    const float* xyzin  = (const float*)d_in[1];
    const float* xyzout = (const float*)d_in[2];
    const float* w1 = (const float*)d_in[3];
    const float* b1 = (const float*)d_in[4];
    const float* g1 = (const float*)d_in[5];
    const float* be1 = (const float*)d_in[6];
    const float* rm1 = (const float*)d_in[7];
    const float* rv1 = (const float*)d_in[8];
    const float* w2 = (const float*)d_in[9];
    const float* b2 = (const float*)d_in[10];
    const float* g2 = (const float*)d_in[11];
    const float* be2 = (const float*)d_in[12];
    const float* rm2 = (const float*)d_in[13];
    const float* rv2 = (const float*)d_in[14];
    const float* w3 = (const float*)d_in[15];
    const float* b3 = (const float*)d_in[16];
    const float* g3 = (const float*)d_in[17];
    const float* be3 = (const float*)d_in[18];
    const float* rm3 = (const float*)d_in[19];
    const float* rv3 = (const float*)d_in[20];
    float* out = (float*)d_out;

    float *act1, *act2, *featT, *pvp;
    int *pip;
    cudaGetSymbolAddress((void**)&act1,  g_act1);
    cudaGetSymbolAddress((void**)&act2,  g_act2);
    cudaGetSymbolAddress((void**)&featT, g_featT);
    cudaGetSymbolAddress((void**)&pvp,   g_pval);
    cudaGetSymbolAddress((void**)&pip,   g_pidx);

    static cudaStream_t s_side = nullptr;
    static cudaEvent_t  ev_fork = nullptr, ev_join = nullptr;
    if (s_side == nullptr) {
        cudaStreamCreateWithFlags(&s_side, cudaStreamNonBlocking);
        cudaEventCreateWithFlags(&ev_fork, cudaEventDisableTiming);
        cudaEventCreateWithFlags(&ev_join, cudaEventDisableTiming);
    }

    cudaEventRecord(ev_fork, 0);
    cudaStreamWaitEvent(s_side, ev_fork, 0);

    // side stream: 3-NN scan (unchanged)
    dim3 scan_grid(M_ / 512, NSEG_, B_);
    scan_kernel<<<scan_grid, 256, 0, s_side>>>(xyzin, xyzout, pvp, pip);
    cudaEventRecord(ev_join, s_side);

    // default stream: tensor-core MLP chain (fp32 activations, in-kernel splits)
    dim3 gemm_grid(NIN_ / 64, B_);
    mlp_mma_kernel<<<gemm_grid, 256>>>(rgb,  w1, b1, g1, be1, rm1, rv1,
                                       act1,  CIN_,  1);
    mlp_mma_kernel<<<gemm_grid, 256>>>(act1, w2, b2, g2, be2, rm2, rv2,
                                       act2,  COUT_, 0);
    mlp_mma_kernel<<<gemm_grid, 256>>>(act2, w3, b3, g3, be3, rm3, rv3,
                                       featT, COUT_, 0);

    cudaStreamWaitEvent(0, ev_join, 0);

    dim3 interp_grid(M_ / 64, B_);
    interp_kernel<<<interp_grid, 128>>>(featT, pvp, pip, out);
}